// round 15
// baseline (speedup 1.0000x reference)
#include <cuda_runtime.h>

// cos(pi*t/16) constants
#define CC1 0.98078528040323044913f
#define CC2 0.92387953251128675613f
#define CC3 0.83146961230254523708f
#define CC4 0.70710678118654752440f
#define CC5 0.55557023301960222474f
#define CC6 0.38268343236508977173f
#define CC7 0.19509032201612826785f

typedef unsigned long long u64;

__device__ __forceinline__ u64 pack2(float lo, float hi) {
    u64 r; asm("mov.b64 %0, {%1, %2};" : "=l"(r) : "f"(lo), "f"(hi)); return r;
}
__device__ __forceinline__ void unpack2(u64 v, float& lo, float& hi) {
    asm("mov.b64 {%0, %1}, %2;" : "=f"(lo), "=f"(hi) : "l"(v));
}
__device__ __forceinline__ u64 add2(u64 a, u64 b) {
    u64 d; asm("add.rn.f32x2 %0, %1, %2;" : "=l"(d) : "l"(a), "l"(b)); return d;
}
__device__ __forceinline__ u64 mul2(u64 a, u64 b) {
    u64 d; asm("mul.rn.f32x2 %0, %1, %2;" : "=l"(d) : "l"(a), "l"(b)); return d;
}
__device__ __forceinline__ u64 fma2(u64 a, u64 b, u64 c) {
    u64 d; asm("fma.rn.f32x2 %0, %1, %2, %3;" : "=l"(d) : "l"(a), "l"(b), "l"(c)); return d;
}

// Packed accumulate with compile-time sign: A += sgn * X * C  (C = packed magnitude)
#define ACC(A, X, K, P)                                                \
    do {                                                               \
        if (SGN[K][P] > 0) (A) = fma2((X), PCC[IDX[K][P]], (A));       \
        else (A) = fma2(mul2((X), PCC[IDX[K][P]]), MIN1, (A));         \
    } while (0)

// Horizontal pass on packed rows: forward masked DCT + inverse, in place.
// Per kept coeff: local partial over lane's 2 cols, 4-lane all-reduce
// (2x shfl_xor + adds), packed-scalar back-substitution.
// Wl is PRE-SCALED by 0.25 (fwd+back => 1/16); l==0 back weight 0.03125.
// HALVE0: fold the vertical-row-0 inverse weight (0.5) into row k==0.
template <int NR, bool HALVE0>
__device__ __forceinline__ void hpassP(u64 (&A)[NR],
                                       const unsigned (&mask)[NR],
                                       const float (&Wl)[6][2])
{
#pragma unroll
    for (int k = 0; k < NR; ++k) {
        const unsigned m = mask[k];
        float a0, a1;
        unpack2(A[k], a0, a1);
        float Bv[6];
#pragma unroll
        for (int l = 0; l < 6; ++l) {
            if ((m >> l) & 1) {
                float p = (l == 0) ? (a0 + a1)
                                   : fmaf(a1, Wl[l][1], a0 * Wl[l][0]);
                p += __shfl_xor_sync(0xffffffffu, p, 1);
                p += __shfl_xor_sync(0xffffffffu, p, 2);
                Bv[l] = p;
            }
        }
        float s0 = 0.f, s1 = 0.f;
#pragma unroll
        for (int l = 0; l < 6; ++l) {
            if ((m >> l) & 1) {
                if (l == 0) { s0 = fmaf(Bv[0], 0.03125f, s0); s1 = fmaf(Bv[0], 0.03125f, s1); }
                else        { s0 = fmaf(Bv[l], Wl[l][0], s0); s1 = fmaf(Bv[l], Wl[l][1], s1); }
            }
        }
        if (HALVE0 && k == 0) { s0 *= 0.5f; s1 *= 0.5f; }
        A[k] = pack2(s0, s1);
    }
}

// Four threads per 8x8 tile, lane q owns columns {2q, 2q+1} as ONE f32x2.
// Luma split: out_c = T9(x_c) + DeltaT16(y); no output color conversion.
// PERSISTENT: one resident wave (grid = 6 CTAs/SM), grid-stride loop over
// tile-slots — removes wave transitions and tail underfill; iteration i+1's
// load batch overlaps iteration i's store tail.
__global__ void __launch_bounds__(128, 6)
jpeg_fused_kernel(const float* __restrict__ in, float* __restrict__ out, int nthr)
{
    const int tid = threadIdx.x;
    const int q = tid & 3;
    const int stride = gridDim.x * blockDim.x;

    // D[k][n] = cos(pi/8 * (n+0.5) * k)
    const float D[8][8] = {
        { 1.f,  1.f,  1.f,  1.f,  1.f,  1.f,  1.f,  1.f},
        { CC1,  CC3,  CC5,  CC7, -CC7, -CC5, -CC3, -CC1},
        { CC2,  CC6, -CC6, -CC2, -CC2, -CC6,  CC6,  CC2},
        { CC3, -CC7, -CC1, -CC5,  CC5,  CC1,  CC7, -CC3},
        { CC4, -CC4, -CC4,  CC4,  CC4, -CC4, -CC4,  CC4},
        { CC5, -CC1,  CC7,  CC3, -CC3, -CC7,  CC1, -CC5},
        { CC6, -CC2,  CC2, -CC6, -CC6,  CC2, -CC2,  CC6},
        { CC7, -CC5,  CC3, -CC1,  CC1, -CC3,  CC5, -CC7}
    };
    // |D[k][p]| = CC_{IDX[k][p]}, sign = SGN[k][p], for p = 0..3 (k = 0 unused)
    const int IDX[7][4] = {
        {0,0,0,0}, {1,3,5,7}, {2,6,6,2}, {3,7,1,5}, {4,4,4,4}, {5,1,7,3}, {6,2,2,6}
    };
    const int SGN[7][4] = {
        {1,1,1,1}, {1,1,1,1}, {1,1,-1,-1}, {1,-1,-1,-1}, {1,-1,-1,1}, {1,-1,1,1}, {1,-1,1,-1}
    };
    const float CCv[8] = {1.f, CC1, CC2, CC3, CC4, CC5, CC6, CC7};

    // Packed broadcast magnitudes (serve stage 1 AND stage 3 — raw scale)
    u64 PCC[8];
#pragma unroll
    for (int i = 1; i < 8; ++i) PCC[i] = pack2(CCv[i], CCv[i]);
    const u64 MIN1 = pack2(-1.f, -1.f);
    // packed colorspace constants for luma
    const u64 PCR = pack2(0.299f, 0.299f);
    const u64 PCG = pack2(0.587f, 0.587f);
    const u64 PCB = pack2(0.114f, 0.114f);

    // kept-coefficient bitmasks per row (luma-split)
    const unsigned MUV[3] = {0x0Fu, 0x07u, 0x03u};                               // 9
    const unsigned MYD[7] = {0x30u, 0x18u, 0x0Cu, 0x0Fu, 0x07u, 0x03u, 0x01u};  // 16

    // Lane-dependent horizontal constants, PRE-SCALED by 0.25 (q fixed across
    // loop iterations -> hoisted). Row 4: Wl[4][1] = -Wl[4][0].
    float Wl[6][2];
#pragma unroll
    for (int l = 1; l < 6; ++l) {
        if (l == 4) continue;
        Wl[l][0] = 0.25f * ((q & 2) ? ((q & 1) ? D[l][6] : D[l][4])
                                    : ((q & 1) ? D[l][2] : D[l][0]));
        Wl[l][1] = 0.25f * ((q & 2) ? ((q & 1) ? D[l][7] : D[l][5])
                                    : ((q & 1) ? D[l][3] : D[l][1]));
    }
    {
        float w4 = (q & 1) ? -0.25f * CC4 : 0.25f * CC4;
        Wl[4][0] = w4;
        Wl[4][1] = -w4;
    }

    const int W = 512;
    const int S = 512 * 512;

    for (int g = blockIdx.x * blockDim.x + tid; g < nthr; g += stride) {
        const int tile = g >> 2;
        const int b  = tile >> 12;
        const int t  = tile & 4095;
        const int ty = t >> 6;
        const int tx = t & 63;

        const size_t off = (size_t)b * (3 * S) + (size_t)(ty * 8) * W
                         + (size_t)(tx * 8) + (size_t)(q * 2);
        const float* p0 = in + off;
        float* o0 = out + off;

        // Packed accumulators: luma rows 0-6, R/G/B rows 0-2
        u64 AY[7], AR[3], AG[3], AB[3];
#pragma unroll
        for (int k = 0; k < 7; ++k) AY[k] = 0ull;
#pragma unroll
        for (int k = 0; k < 3; ++k) { AR[k] = 0ull; AG[k] = 0ull; AB[k] = 0ull; }

        // ---- stage 1: row pairs (p, 7-p): packed s/d, packed luma, packed accumulate ----
#pragma unroll
        for (int p = 0; p < 4; ++p) {
            const int i0 = p * W;
            const int i1 = (7 - p) * W;
            u64 sr, dr, sg, dg, sb, db;
            {
                u64 a = *(const u64*)(p0 + i0);
                u64 c = *(const u64*)(p0 + i1);
                sr = add2(a, c); dr = fma2(c, MIN1, a);
            }
            {
                u64 a = *(const u64*)(p0 + i0 + S);
                u64 c = *(const u64*)(p0 + i1 + S);
                sg = add2(a, c); dg = fma2(c, MIN1, a);
            }
            {
                u64 a = *(const u64*)(p0 + i0 + 2 * S);
                u64 c = *(const u64*)(p0 + i1 + 2 * S);
                sb = add2(a, c); db = fma2(c, MIN1, a);
            }
            // packed luma of s and d
            u64 sy = fma2(sr, PCR, fma2(sg, PCG, mul2(sb, PCB)));
            u64 dy = fma2(dr, PCR, fma2(dg, PCG, mul2(db, PCB)));

            // packed accumulation (even rows <- s, odd rows <- d)
            AY[0] = add2(AY[0], sy);
            ACC(AY[2], sy, 2, p); ACC(AY[4], sy, 4, p); ACC(AY[6], sy, 6, p);
            ACC(AY[1], dy, 1, p); ACC(AY[3], dy, 3, p); ACC(AY[5], dy, 5, p);
            AR[0] = add2(AR[0], sr); ACC(AR[2], sr, 2, p); ACC(AR[1], dr, 1, p);
            AG[0] = add2(AG[0], sg); ACC(AG[2], sg, 2, p); ACC(AG[1], dg, 1, p);
            AB[0] = add2(AB[0], sb); ACC(AB[2], sb, 2, p); ACC(AB[1], db, 1, p);
        }

        // ---- stage 2: horizontal masked round trip; row-0 halving folded in ----
        hpassP<3, true>(AR, MUV, Wl);
        hpassP<3, true>(AG, MUV, Wl);
        hpassP<3, true>(AB, MUV, Wl);
        hpassP<7, true>(AY, MYD, Wl);

        // ---- stage 3: packed even/odd vertical inverse with E/O seeding ----
#pragma unroll
        for (int p = 0; p < 4; ++p) {
            const int i0 = p * W;
            const int i1 = (7 - p) * W;

            u64 ey = AY[0];
            ACC(ey, AY[2], 2, p); ACC(ey, AY[4], 4, p); ACC(ey, AY[6], 6, p);
            u64 oy = mul2(AY[1], PCC[IDX[1][p]]);          // SGN[1][p] always +
            ACC(oy, AY[3], 3, p); ACC(oy, AY[5], 5, p);

            u64 E, O;
            E = add2(ey, AR[0]); ACC(E, AR[2], 2, p);
            O = fma2(AR[1], PCC[IDX[1][p]], oy);
            *(u64*)(o0 + i0)         = add2(E, O);
            *(u64*)(o0 + i1)         = fma2(O, MIN1, E);

            E = add2(ey, AG[0]); ACC(E, AG[2], 2, p);
            O = fma2(AG[1], PCC[IDX[1][p]], oy);
            *(u64*)(o0 + i0 + S)     = add2(E, O);
            *(u64*)(o0 + i1 + S)     = fma2(O, MIN1, E);

            E = add2(ey, AB[0]); ACC(E, AB[2], 2, p);
            O = fma2(AB[1], PCC[IDX[1][p]], oy);
            *(u64*)(o0 + i0 + 2 * S) = add2(E, O);
            *(u64*)(o0 + i1 + 2 * S) = fma2(O, MIN1, E);
        }
    }
}

extern "C" void kernel_launch(void* const* d_in, const int* in_sizes, int n_in,
                              void* d_out, int out_size)
{
    const float* in = (const float*)d_in[0];
    float* out = (float*)d_out;
    const int total = in_sizes[0];               // B*3*512*512
    const int B = total / (3 * 512 * 512);
    const int nthr = B * 64 * 64 * 4;            // 4 threads per tile
    const int threads = 128;
    // One resident wave: 6 CTAs/SM x 148 SMs (never more than the work needs)
    int blocks = 6 * 148;
    const int needed = (nthr + threads - 1) / threads;
    if (blocks > needed) blocks = needed;
    jpeg_fused_kernel<<<blocks, threads>>>(in, out, nthr);
}

// round 16
// speedup vs baseline: 1.1356x; 1.1356x over previous
#include <cuda_runtime.h>

// cos(pi*t/16) constants
#define CC1 0.98078528040323044913f
#define CC2 0.92387953251128675613f
#define CC3 0.83146961230254523708f
#define CC4 0.70710678118654752440f
#define CC5 0.55557023301960222474f
#define CC6 0.38268343236508977173f
#define CC7 0.19509032201612826785f

typedef unsigned long long u64;

__device__ __forceinline__ u64 pack2(float lo, float hi) {
    u64 r; asm("mov.b64 %0, {%1, %2};" : "=l"(r) : "f"(lo), "f"(hi)); return r;
}
__device__ __forceinline__ void unpack2(u64 v, float& lo, float& hi) {
    asm("mov.b64 {%0, %1}, %2;" : "=f"(lo), "=f"(hi) : "l"(v));
}
__device__ __forceinline__ u64 add2(u64 a, u64 b) {
    u64 d; asm("add.rn.f32x2 %0, %1, %2;" : "=l"(d) : "l"(a), "l"(b)); return d;
}
__device__ __forceinline__ u64 mul2(u64 a, u64 b) {
    u64 d; asm("mul.rn.f32x2 %0, %1, %2;" : "=l"(d) : "l"(a), "l"(b)); return d;
}
__device__ __forceinline__ u64 fma2(u64 a, u64 b, u64 c) {
    u64 d; asm("fma.rn.f32x2 %0, %1, %2, %3;" : "=l"(d) : "l"(a), "l"(b), "l"(c)); return d;
}
// Evict-first (streaming) 8-byte store: output is never re-read, so keep it
// from displacing the L2-resident input across graph replays.
__device__ __forceinline__ void st_cs(float* p, u64 v) {
    asm volatile("st.global.cs.b64 [%0], %1;" :: "l"(p), "l"(v) : "memory");
}

// Packed accumulate with compile-time sign: A += sgn * X * C  (C = packed magnitude)
#define ACC(A, X, K, P)                                                \
    do {                                                               \
        if (SGN[K][P] > 0) (A) = fma2((X), PCC[IDX[K][P]], (A));       \
        else (A) = fma2(mul2((X), PCC[IDX[K][P]]), MIN1, (A));         \
    } while (0)

// Horizontal pass on packed rows: forward masked DCT + inverse, in place.
// Per kept coeff: local partial over lane's 2 cols, 4-lane all-reduce
// (2x shfl_xor + adds), packed-scalar back-substitution.
// Wl is PRE-SCALED by 0.25 (fwd+back => 1/16); l==0 back weight 0.03125.
// HALVE0: fold the vertical-row-0 inverse weight (0.5) into row k==0.
template <int NR, bool HALVE0>
__device__ __forceinline__ void hpassP(u64 (&A)[NR],
                                       const unsigned (&mask)[NR],
                                       const float (&Wl)[6][2])
{
#pragma unroll
    for (int k = 0; k < NR; ++k) {
        const unsigned m = mask[k];
        float a0, a1;
        unpack2(A[k], a0, a1);
        float Bv[6];
#pragma unroll
        for (int l = 0; l < 6; ++l) {
            if ((m >> l) & 1) {
                float p = (l == 0) ? (a0 + a1)
                                   : fmaf(a1, Wl[l][1], a0 * Wl[l][0]);
                p += __shfl_xor_sync(0xffffffffu, p, 1);
                p += __shfl_xor_sync(0xffffffffu, p, 2);
                Bv[l] = p;
            }
        }
        float s0 = 0.f, s1 = 0.f;
#pragma unroll
        for (int l = 0; l < 6; ++l) {
            if ((m >> l) & 1) {
                if (l == 0) { s0 = fmaf(Bv[0], 0.03125f, s0); s1 = fmaf(Bv[0], 0.03125f, s1); }
                else        { s0 = fmaf(Bv[l], Wl[l][0], s0); s1 = fmaf(Bv[l], Wl[l][1], s1); }
            }
        }
        if (HALVE0 && k == 0) { s0 *= 0.5f; s1 *= 0.5f; }
        A[k] = pack2(s0, s1);
    }
}

// Four threads per 8x8 tile, lane q owns columns {2q, 2q+1} as ONE f32x2.
// Luma split: out_c = T9(x_c) + DeltaT16(y); no output color conversion.
// R14 structure (empirically fastest); outputs via st.global.cs.
__global__ void __launch_bounds__(128, 6)
jpeg_fused_kernel(const float* __restrict__ in, float* __restrict__ out, int nthr)
{
    const int g = blockIdx.x * blockDim.x + threadIdx.x;
    if (g >= nthr) return;
    const int tile = g >> 2;
    const int q = g & 3;

    // D[k][n] = cos(pi/8 * (n+0.5) * k)
    const float D[8][8] = {
        { 1.f,  1.f,  1.f,  1.f,  1.f,  1.f,  1.f,  1.f},
        { CC1,  CC3,  CC5,  CC7, -CC7, -CC5, -CC3, -CC1},
        { CC2,  CC6, -CC6, -CC2, -CC2, -CC6,  CC6,  CC2},
        { CC3, -CC7, -CC1, -CC5,  CC5,  CC1,  CC7, -CC3},
        { CC4, -CC4, -CC4,  CC4,  CC4, -CC4, -CC4,  CC4},
        { CC5, -CC1,  CC7,  CC3, -CC3, -CC7,  CC1, -CC5},
        { CC6, -CC2,  CC2, -CC6, -CC6,  CC2, -CC2,  CC6},
        { CC7, -CC5,  CC3, -CC1,  CC1, -CC3,  CC5, -CC7}
    };
    // |D[k][p]| = CC_{IDX[k][p]}, sign = SGN[k][p], for p = 0..3 (k = 0 unused)
    const int IDX[7][4] = {
        {0,0,0,0}, {1,3,5,7}, {2,6,6,2}, {3,7,1,5}, {4,4,4,4}, {5,1,7,3}, {6,2,2,6}
    };
    const int SGN[7][4] = {
        {1,1,1,1}, {1,1,1,1}, {1,1,-1,-1}, {1,-1,-1,-1}, {1,-1,-1,1}, {1,-1,1,1}, {1,-1,1,-1}
    };
    const float CCv[8] = {1.f, CC1, CC2, CC3, CC4, CC5, CC6, CC7};

    // Packed broadcast magnitudes (serve stage 1 AND stage 3 — raw scale)
    u64 PCC[8];
#pragma unroll
    for (int i = 1; i < 8; ++i) PCC[i] = pack2(CCv[i], CCv[i]);
    const u64 MIN1 = pack2(-1.f, -1.f);
    // packed colorspace constants for luma
    const u64 PCR = pack2(0.299f, 0.299f);
    const u64 PCG = pack2(0.587f, 0.587f);
    const u64 PCB = pack2(0.114f, 0.114f);

    // kept-coefficient bitmasks per row (luma-split)
    const unsigned MUV[3] = {0x0Fu, 0x07u, 0x03u};                               // 9
    const unsigned MYD[7] = {0x30u, 0x18u, 0x0Cu, 0x0Fu, 0x07u, 0x03u, 0x01u};  // 16

    const int W = 512;
    const int S = 512 * 512;

    const int b  = tile >> 12;
    const int t  = tile & 4095;
    const int ty = t >> 6;
    const int tx = t & 63;

    const size_t off = (size_t)b * (3 * S) + (size_t)(ty * 8) * W
                     + (size_t)(tx * 8) + (size_t)(q * 2);
    const float* p0 = in + off;
    float* o0 = out + off;

    // Packed accumulators: luma rows 0-6, R/G/B rows 0-2
    u64 AY[7], AR[3], AG[3], AB[3];
#pragma unroll
    for (int k = 0; k < 7; ++k) AY[k] = 0ull;
#pragma unroll
    for (int k = 0; k < 3; ++k) { AR[k] = 0ull; AG[k] = 0ull; AB[k] = 0ull; }

    // ---- stage 1: row pairs (p, 7-p): packed s/d, packed luma, packed accumulate ----
#pragma unroll
    for (int p = 0; p < 4; ++p) {
        const int i0 = p * W;
        const int i1 = (7 - p) * W;
        u64 sr, dr, sg, dg, sb, db;
        {
            u64 a = *(const u64*)(p0 + i0);
            u64 c = *(const u64*)(p0 + i1);
            sr = add2(a, c); dr = fma2(c, MIN1, a);
        }
        {
            u64 a = *(const u64*)(p0 + i0 + S);
            u64 c = *(const u64*)(p0 + i1 + S);
            sg = add2(a, c); dg = fma2(c, MIN1, a);
        }
        {
            u64 a = *(const u64*)(p0 + i0 + 2 * S);
            u64 c = *(const u64*)(p0 + i1 + 2 * S);
            sb = add2(a, c); db = fma2(c, MIN1, a);
        }
        // packed luma of s and d (zero unpacks)
        u64 sy = fma2(sr, PCR, fma2(sg, PCG, mul2(sb, PCB)));
        u64 dy = fma2(dr, PCR, fma2(dg, PCG, mul2(db, PCB)));

        // packed accumulation (even rows <- s, odd rows <- d)
        AY[0] = add2(AY[0], sy);
        ACC(AY[2], sy, 2, p); ACC(AY[4], sy, 4, p); ACC(AY[6], sy, 6, p);
        ACC(AY[1], dy, 1, p); ACC(AY[3], dy, 3, p); ACC(AY[5], dy, 5, p);
        AR[0] = add2(AR[0], sr); ACC(AR[2], sr, 2, p); ACC(AR[1], dr, 1, p);
        AG[0] = add2(AG[0], sg); ACC(AG[2], sg, 2, p); ACC(AG[1], dg, 1, p);
        AB[0] = add2(AB[0], sb); ACC(AB[2], sb, 2, p); ACC(AB[1], db, 1, p);
    }

    // Lane-dependent horizontal constants, PRE-SCALED by 0.25 — built after
    // stage 1 (stage-2-only operand). Row 4: Wl[4][1] = -Wl[4][0].
    float Wl[6][2];
#pragma unroll
    for (int l = 1; l < 6; ++l) {
        if (l == 4) continue;
        Wl[l][0] = 0.25f * ((q & 2) ? ((q & 1) ? D[l][6] : D[l][4])
                                    : ((q & 1) ? D[l][2] : D[l][0]));
        Wl[l][1] = 0.25f * ((q & 2) ? ((q & 1) ? D[l][7] : D[l][5])
                                    : ((q & 1) ? D[l][3] : D[l][1]));
    }
    {
        float w4 = (q & 1) ? -0.25f * CC4 : 0.25f * CC4;
        Wl[4][0] = w4;
        Wl[4][1] = -w4;
    }

    // ---- stage 2: horizontal masked round trip; row-0 halving folded in ----
    hpassP<3, true>(AR, MUV, Wl);
    hpassP<3, true>(AG, MUV, Wl);
    hpassP<3, true>(AB, MUV, Wl);
    hpassP<7, true>(AY, MYD, Wl);

    // ---- stage 3: packed even/odd vertical inverse with E/O seeding;
    //      outputs stored evict-first (st.global.cs) ----
#pragma unroll
    for (int p = 0; p < 4; ++p) {
        const int i0 = p * W;
        const int i1 = (7 - p) * W;

        u64 ey = AY[0];
        ACC(ey, AY[2], 2, p); ACC(ey, AY[4], 4, p); ACC(ey, AY[6], 6, p);
        u64 oy = mul2(AY[1], PCC[IDX[1][p]]);          // SGN[1][p] always +
        ACC(oy, AY[3], 3, p); ACC(oy, AY[5], 5, p);

        u64 E, O;
        E = add2(ey, AR[0]); ACC(E, AR[2], 2, p);
        O = fma2(AR[1], PCC[IDX[1][p]], oy);
        st_cs(o0 + i0,         add2(E, O));
        st_cs(o0 + i1,         fma2(O, MIN1, E));

        E = add2(ey, AG[0]); ACC(E, AG[2], 2, p);
        O = fma2(AG[1], PCC[IDX[1][p]], oy);
        st_cs(o0 + i0 + S,     add2(E, O));
        st_cs(o0 + i1 + S,     fma2(O, MIN1, E));

        E = add2(ey, AB[0]); ACC(E, AB[2], 2, p);
        O = fma2(AB[1], PCC[IDX[1][p]], oy);
        st_cs(o0 + i0 + 2 * S, add2(E, O));
        st_cs(o0 + i1 + 2 * S, fma2(O, MIN1, E));
    }
}

extern "C" void kernel_launch(void* const* d_in, const int* in_sizes, int n_in,
                              void* d_out, int out_size)
{
    const float* in = (const float*)d_in[0];
    float* out = (float*)d_out;
    const int total = in_sizes[0];               // B*3*512*512
    const int B = total / (3 * 512 * 512);
    const int nthr = B * 64 * 64 * 4;            // 4 threads per tile
    const int threads = 128;
    const int blocks = (nthr + threads - 1) / threads;
    jpeg_fused_kernel<<<blocks, threads>>>(in, out, nthr);
}